// round 11
// baseline (speedup 1.0000x reference)
#include <cuda_runtime.h>
#include <cstdint>

// SquareRotationalLayer ring gather, H=W=512 (even). SINGLE fused kernel:
//   blocks x in [0,64):   fill path — quadrant closed forms, 4 rings/block
//   blocks x in [64,128): cols path — 32(r) x 64(d) smem transpose of L/R
//                         column interiors (16 r-tiles x 4 d-tiles)
//
// Ring dif: i = 255-dif, jm = 256+dif.
// Quadrant forms (verified incl. b5/b7 crossing quadrant edges at dif>=253):
//   Q1 [0,512):     in[i, clamp(j, i, jm)]
//   Q2 [512,1024):  r=j-511: r<i -> in[i,jm]; i<=r<jm -> cols path;
//                   r>=jm -> in[jm, clamp(1533-j, i, jm)]
//   Q3 [1024,1536): c=1533-j: c>i -> in[jm, min(c,jm)];
//                   c<=i -> in[clamp(2044-j, i, jm), i]
//   Q4 [1536,2048): j<2044: r=2044-j: r<=i -> in[i,i]; i<r<=jm -> cols path;
//                   r>jm -> in[jm,i].   j>=2044: in[i, clamp(j-2044, i, jm)]
// Cols closed forms:
//   right: out[dif, 511+r]  = in[r, 256+dif], r in [255-dif, 255+dif]
//   left:  out[dif, 2044-r] = in[r, 255-dif], r in [256-dif, 256+dif]

static constexpr int HH = 512;
static constexpr int NR = 256;
static constexpr int OW = 2048;

__device__ __forceinline__ int clampi(int x, int lo, int hi) {
    return min(max(x, lo), hi);
}

__global__ __launch_bounds__(512, 4)
void SqRL_fused_kernel(const float* __restrict__ in, float* __restrict__ out) {
    __shared__ float sR[64][33];   // [d_local][r_local], padded
    __shared__ float sL[64][33];

    const int plane = blockIdx.y;
    const float* __restrict__ src = in + (size_t)plane * (HH * HH);

    if (blockIdx.x < 64) {
        // ================= FILL PATH: 4 rings per block =================
        const int dif0 = blockIdx.x << 2;
        float* __restrict__ dst0 = out + ((size_t)plane * NR + dif0) * OW;

        const int j0   = threadIdx.x << 2;   // 4 consecutive output cols
        const int quad = threadIdx.x >> 7;   // warp-uniform quadrant

        #pragma unroll
        for (int dd = 0; dd < 4; dd++) {
            const int dif = dif0 + dd;
            const int i  = 255 - dif;
            const int jm = 256 + dif;
            float* __restrict__ dst = dst0 + (size_t)dd * OW;

            if (quad == 0) {
                // Q1: in[i, clamp(j, i, jm)]
                const float* __restrict__ row = src + i * HH;
                float4 v;
                if (j0 >= i && j0 + 3 <= jm) {
                    v = *reinterpret_cast<const float4*>(row + j0);   // aligned
                } else if (j0 + 3 < i) {
                    const float t = __ldg(row + i);  v = make_float4(t, t, t, t);
                } else if (j0 >= jm) {
                    const float t = __ldg(row + jm); v = make_float4(t, t, t, t);
                } else {
                    v.x = __ldg(row + clampi(j0 + 0, i, jm));
                    v.y = __ldg(row + clampi(j0 + 1, i, jm));
                    v.z = __ldg(row + clampi(j0 + 2, i, jm));
                    v.w = __ldg(row + clampi(j0 + 3, i, jm));
                }
                *reinterpret_cast<float4*>(dst + j0) = v;
            } else if (quad == 1) {
                // Q2: r=j-511
                const int rf = j0 - 511;       // k=0
                const int rl = rf + 3;         // k=3
                if (rl < i) {
                    const float t = __ldg(src + i * HH + jm);
                    *reinterpret_cast<float4*>(dst + j0) = make_float4(t, t, t, t);
                } else if (rf >= jm) {
                    const float* __restrict__ row = src + jm * HH;
                    float4 v;
                    v.x = __ldg(row + clampi(1533 - (j0 + 0), i, jm));
                    v.y = __ldg(row + clampi(1533 - (j0 + 1), i, jm));
                    v.z = __ldg(row + clampi(1533 - (j0 + 2), i, jm));
                    v.w = __ldg(row + clampi(1533 - (j0 + 3), i, jm));
                    *reinterpret_cast<float4*>(dst + j0) = v;
                } else if (rf >= i && rl < jm) {
                    // fully interior -> cols path
                } else {
                    #pragma unroll
                    for (int k = 0; k < 4; k++) {
                        const int j = j0 + k, r = j - 511;
                        if (r < i)        dst[j] = __ldg(src + i * HH + jm);
                        else if (r >= jm) dst[j] = __ldg(src + jm * HH + clampi(1533 - j, i, jm));
                        // i <= r < jm: cols path
                    }
                }
            } else if (quad == 2) {
                // Q3: c=1533-j (descending)
                const int cf = 1533 - j0;      // k=0 (max c)
                const int cl = cf - 3;         // k=3 (min c)
                const float* __restrict__ rowjm = src + jm * HH;
                float4 v;
                if (cl > i && cf <= jm) {
                    // interior bottom row, reversed; cl = 1530-j0 even -> 8B aligned
                    const float2 a = *reinterpret_cast<const float2*>(rowjm + cl);
                    const float2 b = *reinterpret_cast<const float2*>(rowjm + cl + 2);
                    v = make_float4(b.y, b.x, a.y, a.x);
                } else if (cl > jm) {
                    const float t = __ldg(rowjm + jm); v = make_float4(t, t, t, t);
                } else if (cf <= i && (2041 - j0) >= jm) {
                    const float t = __ldg(rowjm + i);  v = make_float4(t, t, t, t);
                } else {
                    #pragma unroll
                    for (int k = 0; k < 4; k++) {
                        const int j = j0 + k, c = 1533 - j;
                        float t;
                        if (c <= i) t = __ldg(src + clampi(2044 - j, i, jm) * HH + i);
                        else        t = __ldg(rowjm + min(c, jm));
                        reinterpret_cast<float*>(&v)[k] = t;
                    }
                }
                *reinterpret_cast<float4*>(dst + j0) = v;
            } else {
                // Q4: r=2044-j (descending); wrap at j>=2044
                if (j0 == 2044) {
                    const float* __restrict__ row = src + i * HH;
                    float4 v;
                    v.x = __ldg(row + clampi(0, i, jm));
                    v.y = __ldg(row + clampi(1, i, jm));
                    v.z = __ldg(row + clampi(2, i, jm));
                    v.w = __ldg(row + clampi(3, i, jm));
                    *reinterpret_cast<float4*>(dst + j0) = v;
                } else {
                    const int rf = 2044 - j0;  // k=0 (max r)
                    const int rl = rf - 3;     // k=3 (min r)
                    if (rf <= i) {
                        const float t = __ldg(src + i * HH + i);
                        *reinterpret_cast<float4*>(dst + j0) = make_float4(t, t, t, t);
                    } else if (rl > jm) {
                        const float t = __ldg(src + jm * HH + i);
                        *reinterpret_cast<float4*>(dst + j0) = make_float4(t, t, t, t);
                    } else if (rl > i && rf <= jm) {
                        // fully interior -> cols path
                    } else {
                        #pragma unroll
                        for (int k = 0; k < 4; k++) {
                            const int j = j0 + k, r = 2044 - j;
                            if (r <= i)      dst[j] = __ldg(src + i * HH + i);
                            else if (r > jm) dst[j] = __ldg(src + jm * HH + i);
                            // i < r <= jm: cols path
                        }
                    }
                }
            }
        }
    } else {
        // ============ COLS PATH: 32(r) x 64(d) transpose tile ============
        const int cx = blockIdx.x - 64;        // 0..63
        const int r0 = (cx & 15) * 32;         // input rows [r0, r0+32)
        const int d0 = (cx >> 4) * 64;         // rings      [d0, d0+64)

        // Cull tiles fully outside both triangles.
        int tmin;
        if (r0 + 31 < 255)      tmin = 255 - (r0 + 31);
        else if (r0 > 256)      tmin = r0 - 256;
        else                    tmin = 0;
        if (d0 + 63 < tmin) return;

        // ---- load phase: lanes span 64 d-values ----
        {
            const int dx = threadIdx.x & 63;   // d lane 0..63
            const int ry = threadIdx.x >> 6;   // 0..7
            #pragma unroll
            for (int yy = 0; yy < 4; yy++) {
                const int rl = ry + 8 * yy;
                const int r  = r0 + rl;
                sR[dx][rl] = __ldg(src + r * HH + (256 + d0 + dx));
                sL[dx][rl] = __ldg(src + r * HH + (255 - d0 - dx));
            }
        }
        __syncthreads();

        // ---- store phase: lanes span 32 r-values (coalesced out rows) ----
        const int rx = threadIdx.x & 31;       // r lane 0..31
        const int dy = threadIdx.x >> 5;       // 0..15

        const int r   = r0 + rx;
        const int thR = max(255 - r, r - 255); // right valid iff dif >= thR
        const int thL = max(256 - r, r - 256); // left  valid iff dif >= thL

        float* __restrict__ dstP = out + (size_t)plane * NR * OW;

        #pragma unroll
        for (int yy = 0; yy < 4; yy++) {
            const int dl  = dy + 16 * yy;      // 0..63
            const int dif = d0 + dl;
            const float vR = sR[dl][rx];
            const float vL = sL[dl][rx];
            float* row = dstP + (size_t)dif * OW;
            if (dif >= thR) row[511 + r]  = vR;   // right: out[dif, 511+r]
            if (dif >= thL) row[2044 - r] = vL;   // left:  out[dif, 2044-r]
        }
    }
}

extern "C" void kernel_launch(void* const* d_in, const int* in_sizes, int n_in,
                              void* d_out, int out_size) {
    const float* x   = (const float*)d_in[0];
    float*       out = (float*)d_out;

    const int BC = in_sizes[0] / (HH * HH);   // 16*32 = 512 planes

    // x: [0,64) fill blocks (4 rings each), [64,128) cols tiles (16 r x 4 d)
    SqRL_fused_kernel<<<dim3(128, BC), 512>>>(x, out);
}

// round 12
// speedup vs baseline: 1.0114x; 1.0114x over previous
#include <cuda_runtime.h>
#include <cstdint>

// SquareRotationalLayer ring gather, H=W=512 (even). SINGLE fused kernel:
//   blocks x in [0,64):  fill path — quadrant closed forms, 4 rings/block
//   blocks x in [64,96): cols path — 64(r) x 64(d) smem transpose of L/R
//                        column interiors (8 r-tiles x 4 d-tiles)
//
// Ring dif: i = 255-dif, jm = 256+dif.
// Quadrant forms (verified incl. b5/b7 crossing quadrant edges at dif>=253):
//   Q1 [0,512):     in[i, clamp(j, i, jm)]
//   Q2 [512,1024):  r=j-511: r<i -> in[i,jm]; i<=r<jm -> cols path;
//                   r>=jm -> in[jm, clamp(1533-j, i, jm)]
//   Q3 [1024,1536): c=1533-j: c>i -> in[jm, min(c,jm)];
//                   c<=i -> in[clamp(2044-j, i, jm), i]
//   Q4 [1536,2048): j<2044: r=2044-j: r<=i -> in[i,i]; i<r<=jm -> cols path;
//                   r>jm -> in[jm,i].   j>=2044: in[i, clamp(j-2044, i, jm)]
// Cols closed forms:
//   right: out[dif, 511+r]  = in[r, 256+dif], r in [255-dif, 255+dif]
//   left:  out[dif, 2044-r] = in[r, 255-dif], r in [256-dif, 256+dif]

static constexpr int HH = 512;
static constexpr int NR = 256;
static constexpr int OW = 2048;

__device__ __forceinline__ int clampi(int x, int lo, int hi) {
    return min(max(x, lo), hi);
}

__global__ __launch_bounds__(512, 4)
void SqRL_fused_kernel(const float* __restrict__ in, float* __restrict__ out) {
    // [d_local][r_local], r padded to 65 so both phases are conflict-free:
    //   load  STS: bank = (65*dx + rl) % 32 = (dx + rl) % 32  (dx spans warp)
    //   store LDS: bank = (65*dl + rx) % 32 = (dl + rx) % 32  (rx spans warp)
    __shared__ float sR[64][65];
    __shared__ float sL[64][65];

    const int plane = blockIdx.y;
    const float* __restrict__ src = in + (size_t)plane * (HH * HH);

    if (blockIdx.x < 64) {
        // ================= FILL PATH: 4 rings per block =================
        const int dif0 = blockIdx.x << 2;
        float* __restrict__ dst0 = out + ((size_t)plane * NR + dif0) * OW;

        const int j0   = threadIdx.x << 2;   // 4 consecutive output cols
        const int quad = threadIdx.x >> 7;   // warp-uniform quadrant

        #pragma unroll
        for (int dd = 0; dd < 4; dd++) {
            const int dif = dif0 + dd;
            const int i  = 255 - dif;
            const int jm = 256 + dif;
            float* __restrict__ dst = dst0 + (size_t)dd * OW;

            if (quad == 0) {
                // Q1: in[i, clamp(j, i, jm)]
                const float* __restrict__ row = src + i * HH;
                float4 v;
                if (j0 >= i && j0 + 3 <= jm) {
                    v = *reinterpret_cast<const float4*>(row + j0);   // aligned
                } else if (j0 + 3 < i) {
                    const float t = __ldg(row + i);  v = make_float4(t, t, t, t);
                } else if (j0 >= jm) {
                    const float t = __ldg(row + jm); v = make_float4(t, t, t, t);
                } else {
                    v.x = __ldg(row + clampi(j0 + 0, i, jm));
                    v.y = __ldg(row + clampi(j0 + 1, i, jm));
                    v.z = __ldg(row + clampi(j0 + 2, i, jm));
                    v.w = __ldg(row + clampi(j0 + 3, i, jm));
                }
                *reinterpret_cast<float4*>(dst + j0) = v;
            } else if (quad == 1) {
                // Q2: r=j-511
                const int rf = j0 - 511;       // k=0
                const int rl = rf + 3;         // k=3
                if (rl < i) {
                    const float t = __ldg(src + i * HH + jm);
                    *reinterpret_cast<float4*>(dst + j0) = make_float4(t, t, t, t);
                } else if (rf >= jm) {
                    const float* __restrict__ row = src + jm * HH;
                    float4 v;
                    v.x = __ldg(row + clampi(1533 - (j0 + 0), i, jm));
                    v.y = __ldg(row + clampi(1533 - (j0 + 1), i, jm));
                    v.z = __ldg(row + clampi(1533 - (j0 + 2), i, jm));
                    v.w = __ldg(row + clampi(1533 - (j0 + 3), i, jm));
                    *reinterpret_cast<float4*>(dst + j0) = v;
                } else if (rf >= i && rl < jm) {
                    // fully interior -> cols path
                } else {
                    #pragma unroll
                    for (int k = 0; k < 4; k++) {
                        const int j = j0 + k, r = j - 511;
                        if (r < i)        dst[j] = __ldg(src + i * HH + jm);
                        else if (r >= jm) dst[j] = __ldg(src + jm * HH + clampi(1533 - j, i, jm));
                        // i <= r < jm: cols path
                    }
                }
            } else if (quad == 2) {
                // Q3: c=1533-j (descending)
                const int cf = 1533 - j0;      // k=0 (max c)
                const int cl = cf - 3;         // k=3 (min c)
                const float* __restrict__ rowjm = src + jm * HH;
                float4 v;
                if (cl > i && cf <= jm) {
                    // interior bottom row, reversed; cl = 1530-j0 even -> 8B aligned
                    const float2 a = *reinterpret_cast<const float2*>(rowjm + cl);
                    const float2 b = *reinterpret_cast<const float2*>(rowjm + cl + 2);
                    v = make_float4(b.y, b.x, a.y, a.x);
                } else if (cl > jm) {
                    const float t = __ldg(rowjm + jm); v = make_float4(t, t, t, t);
                } else if (cf <= i && (2041 - j0) >= jm) {
                    const float t = __ldg(rowjm + i);  v = make_float4(t, t, t, t);
                } else {
                    #pragma unroll
                    for (int k = 0; k < 4; k++) {
                        const int j = j0 + k, c = 1533 - j;
                        float t;
                        if (c <= i) t = __ldg(src + clampi(2044 - j, i, jm) * HH + i);
                        else        t = __ldg(rowjm + min(c, jm));
                        reinterpret_cast<float*>(&v)[k] = t;
                    }
                }
                *reinterpret_cast<float4*>(dst + j0) = v;
            } else {
                // Q4: r=2044-j (descending); wrap at j>=2044
                if (j0 == 2044) {
                    const float* __restrict__ row = src + i * HH;
                    float4 v;
                    v.x = __ldg(row + clampi(0, i, jm));
                    v.y = __ldg(row + clampi(1, i, jm));
                    v.z = __ldg(row + clampi(2, i, jm));
                    v.w = __ldg(row + clampi(3, i, jm));
                    *reinterpret_cast<float4*>(dst + j0) = v;
                } else {
                    const int rf = 2044 - j0;  // k=0 (max r)
                    const int rl = rf - 3;     // k=3 (min r)
                    if (rf <= i) {
                        const float t = __ldg(src + i * HH + i);
                        *reinterpret_cast<float4*>(dst + j0) = make_float4(t, t, t, t);
                    } else if (rl > jm) {
                        const float t = __ldg(src + jm * HH + i);
                        *reinterpret_cast<float4*>(dst + j0) = make_float4(t, t, t, t);
                    } else if (rl > i && rf <= jm) {
                        // fully interior -> cols path
                    } else {
                        #pragma unroll
                        for (int k = 0; k < 4; k++) {
                            const int j = j0 + k, r = 2044 - j;
                            if (r <= i)      dst[j] = __ldg(src + i * HH + i);
                            else if (r > jm) dst[j] = __ldg(src + jm * HH + i);
                            // i < r <= jm: cols path
                        }
                    }
                }
            }
        }
    } else {
        // ============ COLS PATH: 64(r) x 64(d) transpose tile ============
        const int cx = blockIdx.x - 64;        // 0..31
        const int r0 = (cx & 7) * 64;          // input rows [r0, r0+64)
        const int d0 = (cx >> 3) * 64;         // rings      [d0, d0+64)

        // Cull tiles fully outside both triangles.
        int tmin;
        if (r0 + 63 < 255)      tmin = 255 - (r0 + 63);
        else if (r0 > 256)      tmin = r0 - 256;
        else                    tmin = 0;
        if (d0 + 63 < tmin) return;

        // ---- load phase: lanes span 64 d-values; 8 rows per thread ----
        {
            const int dx = threadIdx.x & 63;   // d lane 0..63
            const int ry = threadIdx.x >> 6;   // 0..7
            const float* __restrict__ pR = src + (r0 + ry) * HH + (256 + d0 + dx);
            const float* __restrict__ pL = src + (r0 + ry) * HH + (255 - d0 - dx);
            #pragma unroll
            for (int yy = 0; yy < 8; yy++) {
                const int rl = ry + 8 * yy;
                sR[dx][rl] = __ldg(pR + yy * (8 * HH));
                sL[dx][rl] = __ldg(pL + yy * (8 * HH));
            }
        }
        __syncthreads();

        // ---- store phase: lanes span 32 consecutive r (coalesced) ----
        const int rx = threadIdx.x & 31;       // r lane 0..31
        const int dy = threadIdx.x >> 5;       // 0..15

        float* __restrict__ dstP = out + (size_t)plane * NR * OW;

        #pragma unroll
        for (int rh = 0; rh < 2; rh++) {       // two 32-row halves
            const int rloc = rx + 32 * rh;
            const int r    = r0 + rloc;
            const int thR  = max(255 - r, r - 255);  // right valid iff dif >= thR
            const int thL  = max(256 - r, r - 256);  // left  valid iff dif >= thL
            #pragma unroll
            for (int yy = 0; yy < 4; yy++) {
                const int dl  = dy + 16 * yy;  // 0..63
                const int dif = d0 + dl;
                const float vR = sR[dl][rloc];
                const float vL = sL[dl][rloc];
                float* row = dstP + (size_t)dif * OW;
                if (dif >= thR) row[511 + r]  = vR;   // right: out[dif, 511+r]
                if (dif >= thL) row[2044 - r] = vL;   // left:  out[dif, 2044-r]
            }
        }
    }
}

extern "C" void kernel_launch(void* const* d_in, const int* in_sizes, int n_in,
                              void* d_out, int out_size) {
    const float* x   = (const float*)d_in[0];
    float*       out = (float*)d_out;

    const int BC = in_sizes[0] / (HH * HH);   // 16*32 = 512 planes

    // x: [0,64) fill blocks (4 rings each), [64,96) cols tiles (8 r x 4 d)
    SqRL_fused_kernel<<<dim3(96, BC), 512>>>(x, out);
}

// round 13
// speedup vs baseline: 1.0288x; 1.0173x over previous
#include <cuda_runtime.h>
#include <cstdint>

// SquareRotationalLayer ring gather, H=W=512 (even). SINGLE fused kernel:
//   blocks x in [0,64):  fill path — quadrant closed forms, 4 rings/block
//   blocks x in [64,84): cols path — 64(r) x 64(d) smem transpose of L/R
//                        column interiors; only the 20 surviving tiles of the
//                        8x4 tiling are enumerated (12 fully-culled tiles
//                        removed from the grid).
//
// Ring dif: i = 255-dif, jm = 256+dif.
// Quadrant forms (verified incl. b5/b7 crossing quadrant edges at dif>=253):
//   Q1 [0,512):     in[i, clamp(j, i, jm)]
//   Q2 [512,1024):  r=j-511: r<i -> in[i,jm]; i<=r<jm -> cols path;
//                   r>=jm -> in[jm, clamp(1533-j, i, jm)]
//   Q3 [1024,1536): c=1533-j: c>i -> in[jm, min(c,jm)];
//                   c<=i -> in[clamp(2044-j, i, jm), i]
//   Q4 [1536,2048): j<2044: r=2044-j: r<=i -> in[i,i]; i<r<=jm -> cols path;
//                   r>jm -> in[jm,i].   j>=2044: in[i, clamp(j-2044, i, jm)]
// Cols closed forms:
//   right: out[dif, 511+r]  = in[r, 256+dif], r in [255-dif, 255+dif]
//   left:  out[dif, 2044-r] = in[r, 255-dif], r in [256-dif, 256+dif]
// Surviving 64x64 tiles (rt = r0/64, dt = d0/64), keep iff d0+63 >= tmin(r0):
//   dt=0: rt {3,4}; dt=1: rt {2..5}; dt=2: rt {1..6}; dt=3: rt {0..7} -> 20.

static constexpr int HH = 512;
static constexpr int NR = 256;
static constexpr int OW = 2048;

__device__ __forceinline__ int clampi(int x, int lo, int hi) {
    return min(max(x, lo), hi);
}

__global__ __launch_bounds__(512, 4)
void SqRL_fused_kernel(const float* __restrict__ in, float* __restrict__ out) {
    // [d_local][r_local], r padded to 65: store-phase LDS is conflict-free
    // (bank = (dl + rx) % 32 with rx spanning the warp). Load-phase STS pairs
    // from LDG.64 are 2-way conflicted — accepted, smem is not the limiter.
    __shared__ float sR[64][65];
    __shared__ float sL[64][65];

    const int plane = blockIdx.y;
    const float* __restrict__ src = in + (size_t)plane * (HH * HH);

    if (blockIdx.x < 64) {
        // ================= FILL PATH: 4 rings per block =================
        const int dif0 = blockIdx.x << 2;
        float* __restrict__ dst0 = out + ((size_t)plane * NR + dif0) * OW;

        const int j0   = threadIdx.x << 2;   // 4 consecutive output cols
        const int quad = threadIdx.x >> 7;   // warp-uniform quadrant

        #pragma unroll
        for (int dd = 0; dd < 4; dd++) {
            const int dif = dif0 + dd;
            const int i  = 255 - dif;
            const int jm = 256 + dif;
            float* __restrict__ dst = dst0 + (size_t)dd * OW;

            if (quad == 0) {
                // Q1: in[i, clamp(j, i, jm)]
                const float* __restrict__ row = src + i * HH;
                float4 v;
                if (j0 >= i && j0 + 3 <= jm) {
                    v = *reinterpret_cast<const float4*>(row + j0);   // aligned
                } else if (j0 + 3 < i) {
                    const float t = __ldg(row + i);  v = make_float4(t, t, t, t);
                } else if (j0 >= jm) {
                    const float t = __ldg(row + jm); v = make_float4(t, t, t, t);
                } else {
                    v.x = __ldg(row + clampi(j0 + 0, i, jm));
                    v.y = __ldg(row + clampi(j0 + 1, i, jm));
                    v.z = __ldg(row + clampi(j0 + 2, i, jm));
                    v.w = __ldg(row + clampi(j0 + 3, i, jm));
                }
                *reinterpret_cast<float4*>(dst + j0) = v;
            } else if (quad == 1) {
                // Q2: r=j-511
                const int rf = j0 - 511;       // k=0
                const int rl = rf + 3;         // k=3
                if (rl < i) {
                    const float t = __ldg(src + i * HH + jm);
                    *reinterpret_cast<float4*>(dst + j0) = make_float4(t, t, t, t);
                } else if (rf >= jm) {
                    const float* __restrict__ row = src + jm * HH;
                    float4 v;
                    v.x = __ldg(row + clampi(1533 - (j0 + 0), i, jm));
                    v.y = __ldg(row + clampi(1533 - (j0 + 1), i, jm));
                    v.z = __ldg(row + clampi(1533 - (j0 + 2), i, jm));
                    v.w = __ldg(row + clampi(1533 - (j0 + 3), i, jm));
                    *reinterpret_cast<float4*>(dst + j0) = v;
                } else if (rf >= i && rl < jm) {
                    // fully interior -> cols path
                } else {
                    #pragma unroll
                    for (int k = 0; k < 4; k++) {
                        const int j = j0 + k, r = j - 511;
                        if (r < i)        dst[j] = __ldg(src + i * HH + jm);
                        else if (r >= jm) dst[j] = __ldg(src + jm * HH + clampi(1533 - j, i, jm));
                        // i <= r < jm: cols path
                    }
                }
            } else if (quad == 2) {
                // Q3: c=1533-j (descending)
                const int cf = 1533 - j0;      // k=0 (max c)
                const int cl = cf - 3;         // k=3 (min c)
                const float* __restrict__ rowjm = src + jm * HH;
                float4 v;
                if (cl > i && cf <= jm) {
                    // interior bottom row, reversed; cl = 1530-j0 even -> 8B aligned
                    const float2 a = *reinterpret_cast<const float2*>(rowjm + cl);
                    const float2 b = *reinterpret_cast<const float2*>(rowjm + cl + 2);
                    v = make_float4(b.y, b.x, a.y, a.x);
                } else if (cl > jm) {
                    const float t = __ldg(rowjm + jm); v = make_float4(t, t, t, t);
                } else if (cf <= i && (2041 - j0) >= jm) {
                    const float t = __ldg(rowjm + i);  v = make_float4(t, t, t, t);
                } else {
                    #pragma unroll
                    for (int k = 0; k < 4; k++) {
                        const int j = j0 + k, c = 1533 - j;
                        float t;
                        if (c <= i) t = __ldg(src + clampi(2044 - j, i, jm) * HH + i);
                        else        t = __ldg(rowjm + min(c, jm));
                        reinterpret_cast<float*>(&v)[k] = t;
                    }
                }
                *reinterpret_cast<float4*>(dst + j0) = v;
            } else {
                // Q4: r=2044-j (descending); wrap at j>=2044
                if (j0 == 2044) {
                    const float* __restrict__ row = src + i * HH;
                    float4 v;
                    v.x = __ldg(row + clampi(0, i, jm));
                    v.y = __ldg(row + clampi(1, i, jm));
                    v.z = __ldg(row + clampi(2, i, jm));
                    v.w = __ldg(row + clampi(3, i, jm));
                    *reinterpret_cast<float4*>(dst + j0) = v;
                } else {
                    const int rf = 2044 - j0;  // k=0 (max r)
                    const int rl = rf - 3;     // k=3 (min r)
                    if (rf <= i) {
                        const float t = __ldg(src + i * HH + i);
                        *reinterpret_cast<float4*>(dst + j0) = make_float4(t, t, t, t);
                    } else if (rl > jm) {
                        const float t = __ldg(src + jm * HH + i);
                        *reinterpret_cast<float4*>(dst + j0) = make_float4(t, t, t, t);
                    } else if (rl > i && rf <= jm) {
                        // fully interior -> cols path
                    } else {
                        #pragma unroll
                        for (int k = 0; k < 4; k++) {
                            const int j = j0 + k, r = 2044 - j;
                            if (r <= i)      dst[j] = __ldg(src + i * HH + i);
                            else if (r > jm) dst[j] = __ldg(src + jm * HH + i);
                            // i < r <= jm: cols path
                        }
                    }
                }
            }
        }
    } else {
        // ============ COLS PATH: 64(r) x 64(d) transpose tile ============
        // Map cx in [0,20) to surviving (rt, dt):
        //   dt tier starts at {0,2,6,12}; rt = (3-dt) + (cx - start).
        const int cx = blockIdx.x - 64;        // 0..19
        int dt, start;
        if (cx < 2)       { dt = 0; start = 0;  }
        else if (cx < 6)  { dt = 1; start = 2;  }
        else if (cx < 12) { dt = 2; start = 6;  }
        else              { dt = 3; start = 12; }
        const int rt = (3 - dt) + (cx - start);
        const int r0 = rt * 64;                // input rows [r0, r0+64)
        const int d0 = dt * 64;                // rings      [d0, d0+64)

        // ---- load phase: LDG.64 pairs over 64 d-values; 4 rows/thread ----
        {
            const int lx = threadIdx.x & 31;   // d-pair lane 0..31
            const int ry = threadIdx.x >> 5;   // 0..15
            const float* __restrict__ pR = src + (r0 + ry) * HH + (256 + d0 + 2 * lx);
            const float* __restrict__ pL = src + (r0 + ry) * HH + (254 - d0 - 2 * lx);
            #pragma unroll
            for (int yy = 0; yy < 4; yy++) {
                const int rl = ry + 16 * yy;
                const float2 vR = *reinterpret_cast<const float2*>(pR + yy * (16 * HH));
                const float2 vL = *reinterpret_cast<const float2*>(pL + yy * (16 * HH));
                sR[2 * lx + 0][rl] = vR.x;     // col 256+d0+2lx   -> dloc 2lx
                sR[2 * lx + 1][rl] = vR.y;     // col 256+d0+2lx+1 -> dloc 2lx+1
                sL[2 * lx + 0][rl] = vL.y;     // col 255-d0-2lx   -> dloc 2lx
                sL[2 * lx + 1][rl] = vL.x;     // col 254-d0-2lx   -> dloc 2lx+1
            }
        }
        __syncthreads();

        // ---- store phase: lanes span 32 consecutive r (coalesced) ----
        const int rx = threadIdx.x & 31;       // r lane 0..31
        const int dy = threadIdx.x >> 5;       // 0..15

        float* __restrict__ dstP = out + (size_t)plane * NR * OW;

        #pragma unroll
        for (int rh = 0; rh < 2; rh++) {       // two 32-row halves
            const int rloc = rx + 32 * rh;
            const int r    = r0 + rloc;
            const int thR  = max(255 - r, r - 255);  // right valid iff dif >= thR
            const int thL  = max(256 - r, r - 256);  // left  valid iff dif >= thL
            #pragma unroll
            for (int yy = 0; yy < 4; yy++) {
                const int dl  = dy + 16 * yy;  // 0..63
                const int dif = d0 + dl;
                const float vR = sR[dl][rloc];
                const float vL = sL[dl][rloc];
                float* row = dstP + (size_t)dif * OW;
                if (dif >= thR) row[511 + r]  = vR;   // right: out[dif, 511+r]
                if (dif >= thL) row[2044 - r] = vL;   // left:  out[dif, 2044-r]
            }
        }
    }
}

extern "C" void kernel_launch(void* const* d_in, const int* in_sizes, int n_in,
                              void* d_out, int out_size) {
    const float* x   = (const float*)d_in[0];
    float*       out = (float*)d_out;

    const int BC = in_sizes[0] / (HH * HH);   // 16*32 = 512 planes

    // x: [0,64) fill blocks (4 rings each), [64,84) surviving cols tiles
    SqRL_fused_kernel<<<dim3(84, BC), 512>>>(x, out);
}